// round 10
// baseline (speedup 1.0000x reference)
#include <cuda_runtime.h>
#include <math.h>

#define NMAT 256
#define DIM 64
#define DD 4096
#define K_LOG 13
#define K_EXP 11

// smem: Ys(4096 f) | Bd0(8192 f, dup f32x2) | Bd1(8192 f) | extra(64 f)
#define SMEMX ((4096 + 8192 + 8192 + 64) * 4)

// ---------------- device scratch (no allocations allowed) ----------------
__device__ float g_L[NMAT * DD];
__device__ float g_numK[NMAT * DD];
__device__ float g_W[NMAT * NMAT];
__device__ float g_gramP[8 * NMAT * NMAT];
__device__ float g_sq[NMAT];
__device__ float g_s[NMAT];
__device__ float g_rs[NMAT];
__device__ float g_cs[NMAT];

// ---------------- packed f32x2 helpers ----------------
__device__ __forceinline__ unsigned long long ffma2(unsigned long long a,
                                                    unsigned long long b,
                                                    unsigned long long c) {
    unsigned long long d;
    asm("fma.rn.f32x2 %0, %1, %2, %3;" : "=l"(d) : "l"(a), "l"(b), "l"(c));
    return d;
}
__device__ __forceinline__ unsigned long long bcast2(float x) {
    unsigned long long d;
    unsigned int xi = __float_as_uint(x);
    asm("mov.b64 %0, {%1, %1};" : "=l"(d) : "r"(xi));
    return d;
}
__device__ __forceinline__ float2 unpk(unsigned long long v) {
    unsigned int a, b;
    asm("mov.b64 {%0, %1}, %2;" : "=r"(a), "=r"(b) : "l"(v));
    return make_float2(__uint_as_float(a), __uint_as_float(b));
}

// ============ one Clenshaw step, register-resident prev tile ============
// T (32 regs) holds b_{k+2} tile on entry, b_k tile on exit.
// BdR: duplicated f32x2 view of b_{k+1}; BdW: dup store target (if STORE).
template<bool STORE>
__device__ __forceinline__ void clen_step(const float* __restrict__ Ys,
                                          const float* __restrict__ BdR,
                                          float* __restrict__ BdW,
                                          float* T, int i0, int j0,
                                          float ck, float fac) {
    unsigned long long acc[4][4];
#pragma unroll
    for (int a = 0; a < 4; ++a)
#pragma unroll
        for (int c = 0; c < 4; ++c) acc[a][c] = 0ull;

#pragma unroll 8
    for (int k = 0; k < 64; ++k) {
        const ulonglong2 a01 = *(const ulonglong2*)(Ys + k * 64 + i0);
        const ulonglong2 a23 = *(const ulonglong2*)(Ys + k * 64 + i0 + 4);
        const ulonglong2 b01 = *(const ulonglong2*)(BdR + (k * 64 + j0) * 2);
        const ulonglong2 b23 = *(const ulonglong2*)(BdR + (k * 64 + j0) * 2 + 4);  // FIXED (+8 -> +4)
        acc[0][0] = ffma2(a01.x, b01.x, acc[0][0]); acc[1][0] = ffma2(a01.y, b01.x, acc[1][0]);
        acc[2][0] = ffma2(a23.x, b01.x, acc[2][0]); acc[3][0] = ffma2(a23.y, b01.x, acc[3][0]);
        acc[0][1] = ffma2(a01.x, b01.y, acc[0][1]); acc[1][1] = ffma2(a01.y, b01.y, acc[1][1]);
        acc[2][1] = ffma2(a23.x, b01.y, acc[2][1]); acc[3][1] = ffma2(a23.y, b01.y, acc[3][1]);
        acc[0][2] = ffma2(a01.x, b23.x, acc[0][2]); acc[1][2] = ffma2(a01.y, b23.x, acc[1][2]);
        acc[2][2] = ffma2(a23.x, b23.x, acc[2][2]); acc[3][2] = ffma2(a23.y, b23.x, acc[3][2]);
        acc[0][3] = ffma2(a01.x, b23.y, acc[0][3]); acc[1][3] = ffma2(a01.y, b23.y, acc[1][3]);
        acc[2][3] = ffma2(a23.x, b23.y, acc[2][3]); acc[3][3] = ffma2(a23.y, b23.y, acc[3][3]);
    }

#pragma unroll
    for (int ip = 0; ip < 4; ++ip) {
        float2 p0 = unpk(acc[ip][0]), p1 = unpk(acc[ip][1]);
        float2 p2 = unpk(acc[ip][2]), p3 = unpk(acc[ip][3]);
        float vr[2][4] = {{p0.x, p1.x, p2.x, p3.x}, {p0.y, p1.y, p2.y, p3.y}};
#pragma unroll
        for (int t = 0; t < 2; ++t) {
            const int r = 2 * ip + t;
            const int gi = i0 + r;
            float4 nv;
            nv.x = fmaf(fac, vr[t][0], -T[r * 4 + 0]);
            nv.y = fmaf(fac, vr[t][1], -T[r * 4 + 1]);
            nv.z = fmaf(fac, vr[t][2], -T[r * 4 + 2]);
            nv.w = fmaf(fac, vr[t][3], -T[r * 4 + 3]);
            if (gi == j0 + 0) nv.x += ck;
            if (gi == j0 + 1) nv.y += ck;
            if (gi == j0 + 2) nv.z += ck;
            if (gi == j0 + 3) nv.w += ck;
            T[r * 4 + 0] = nv.x; T[r * 4 + 1] = nv.y;
            T[r * 4 + 2] = nv.z; T[r * 4 + 3] = nv.w;
            if (STORE) {
                *(float4*)(BdW + (gi * 64 + j0) * 2)     = make_float4(nv.x, nv.x, nv.y, nv.y);
                *(float4*)(BdW + (gi * 64 + j0) * 2 + 4) = make_float4(nv.z, nv.z, nv.w, nv.w);
            }
        }
    }
    if (STORE) __syncthreads();
}

// scale Ys in place, init Bd0 = dup(cK I), tiles tA=0 / tB=cK-diag
__device__ __forceinline__ void scale_and_init(float* Ys, float* Bd0, int tid,
                                               float m, float invh, float cK,
                                               float* tA, float* tB, int i0, int j0) {
#pragma unroll
    for (int u = 0; u < 8; ++u) {
        int e = (u * 128 + tid) * 4;
        float4 x = *(const float4*)(Ys + e);
        int i = e >> 6, jb = e & 63;
        x.x = (x.x - ((jb + 0) == i ? m : 0.f)) * invh;
        x.y = (x.y - ((jb + 1) == i ? m : 0.f)) * invh;
        x.z = (x.z - ((jb + 2) == i ? m : 0.f)) * invh;
        x.w = (x.w - ((jb + 3) == i ? m : 0.f)) * invh;
        *(float4*)(Ys + e) = x;
    }
#pragma unroll
    for (int u = 0; u < 16; ++u) {
        int f = u * 128 + tid;          // float4 index 0..2047
        int P = f * 2;                  // dup-pair (k,j)
        int k = P >> 6, j = P & 63;
        float v0 = (k == j)     ? cK : 0.f;
        float v1 = (k == j + 1) ? cK : 0.f;
        *(float4*)(Bd0 + f * 4) = make_float4(v0, v0, v1, v1);
    }
#pragma unroll
    for (int r = 0; r < 8; ++r)
#pragma unroll
        for (int j = 0; j < 4; ++j) {
            tA[r * 4 + j] = 0.f;
            tB[r * 4 + j] = (i0 + r == j0 + j) ? cK : 0.f;
        }
    __syncthreads();
}

// regular steps k=K-1..1 (count K-1 must be even), final k=0 -> result in tA
template<int K>
__device__ __forceinline__ void clenshaw_run(const float* Ys, float* Bd0, float* Bd1,
                                             const float* cc, float* tA, float* tB,
                                             int i0, int j0) {
    for (int s = 0; s < (K - 1) / 2; ++s) {
        float c1 = cc[K - 1 - 2 * s];
        float c2 = cc[K - 2 - 2 * s];
        clen_step<true>(Ys, Bd0, Bd1, tA, i0, j0, c1, 2.f);
        clen_step<true>(Ys, Bd1, Bd0, tB, i0, j0, c2, 2.f);
    }
    clen_step<false>(Ys, Bd0, nullptr, tA, i0, j0, cc[0], 1.f);
}

// ===== cheb_log: load, Gershgorin + power-iter bound, coeffs, Clenshaw, L + stats =====
__global__ __launch_bounds__(128) void cheb_log_kernel(const float* __restrict__ X) {
    extern __shared__ float sm[];
    float* Ys = sm;
    float* Bd0 = sm + 4096;
    float* Bd1 = sm + 12288;
    float* extra = sm + 20480;     // [0..K] coeffs, [36]=m, [37]=h
    int b = blockIdx.x, tid = threadIdx.x;
    const float* sb = X + (size_t)b * DD;

    int r = tid >> 1, q = tid & 1;
    float pa = 0.f;
#pragma unroll
    for (int u = 0; u < 8; ++u) {
        int cb = q * 32 + u * 4;
        float4 x = *(const float4*)(sb + r * 64 + cb);
        *(float4*)(Ys + r * 64 + cb) = x;
        pa += fabsf(x.x) + fabsf(x.y) + fabsf(x.z) + fabsf(x.w);
    }
    Bd1[tid] = pa;
    __syncthreads();
    if (tid < 64) Bd1[128 + tid] = Bd1[2 * tid] + Bd1[2 * tid + 1];

    // power iteration (19 matvecs), column-major reads
    float* v = Bd1 + 256;
    float* w = Bd1 + 320;
    if (tid < 64) v[tid] = 1.f + 0.0123f * (float)tid;
    __syncthreads();
    for (int it = 0; it < 19; ++it) {
        float p = 0.f;
#pragma unroll 8
        for (int c = 0; c < 32; ++c)
            p = fmaf(Ys[(q * 32 + c) * 64 + r], v[q * 32 + c], p);
        p += __shfl_xor_sync(0xffffffffu, p, 1);
        if (q == 0) w[r] = p;
        __syncthreads();
        if (it < 18) {
            if (tid < 64) v[tid] = w[tid] * 0.25f;   // mild rescale vs overflow
            __syncthreads();
        }
    }
    if (tid == 0) {
        float vw = 0.f, vv = 0.f;
        for (int t2 = 0; t2 < 64; ++t2) { vw += v[t2] * w[t2]; vv += v[t2] * v[t2]; }
        float rho = vw / vv;
        float gersh = 0.f;
        for (int t2 = 0; t2 < 64; ++t2) gersh = fmaxf(gersh, Bd1[128 + t2]);
        float bb = fminf(gersh + 1e-3f, fmaf(1.12f, rho, 0.45f));
        if (bb < 0.6f) bb = 0.6f;
        const float a = 0.49f;
        extra[36] = 0.5f * (a + bb);
        extra[37] = 0.5f * (bb - a);
    }
    __syncthreads();
    if (tid <= K_LOG) {
        float m = extra[36], h = extra[37];
        float beta = h / m;
        float s = sqrtf(fmaxf(1.f - beta * beta, 0.f));
        float qz = (1.f - s) / beta;
        if (tid == 0) extra[0] = logf(m) - logf(1.f + qz * qz);
        else {
            float qk = exp2f((float)tid * log2f(qz));
            extra[tid] = 2.f * ((tid & 1) ? 1.f : -1.f) * qk / (float)tid;
        }
    }
    __syncthreads();

    const int i0 = (tid >> 4) << 3, j0 = (tid & 15) << 2;
    float tA[32], tB[32];
    scale_and_init(Ys, Bd0, tid, extra[36], 1.f / extra[37], extra[K_LOG], tA, tB, i0, j0);
    clenshaw_run<K_LOG>(Ys, Bd0, Bd1, extra, tA, tB, i0, j0);

    float* db = g_L + (size_t)b * DD;
    float sqa = 0.f, ssum = 0.f;
#pragma unroll
    for (int rr = 0; rr < 8; ++rr) {
        float4 o = make_float4(tA[rr * 4], tA[rr * 4 + 1], tA[rr * 4 + 2], tA[rr * 4 + 3]);
        *(float4*)(db + (i0 + rr) * 64 + j0) = o;
        sqa = fmaf(o.x, o.x, fmaf(o.y, o.y, fmaf(o.z, o.z, fmaf(o.w, o.w, sqa))));
        ssum += o.x + o.y + o.z + o.w;
    }
    __syncthreads();
    Bd1[tid] = sqa;
    Bd1[128 + tid] = ssum;
    __syncthreads();
    for (int off = 64; off > 0; off >>= 1) {
        if (tid < off) { Bd1[tid] += Bd1[tid + off]; Bd1[128 + tid] += Bd1[128 + tid + off]; }
        __syncthreads();
    }
    if (tid == 0) { g_sq[b] = Bd1[0]; g_s[b] = Bd1[128]; }
}

// ===== gram: split-K GEMM, f32x2 packed along k =====
#define GST 68
__global__ __launch_bounds__(256) void gram_kernel() {
    __shared__ float Ti[64 * GST], Tj[64 * GST];
    int tid = threadIdx.x;
    int j0g = blockIdx.x * 64, i0g = blockIdx.y * 64, z = blockIdx.z;
    int ti = tid >> 4, tj = tid & 15;
    int i0 = ti * 4, j0 = tj * 4;

    unsigned long long acc[4][4];
#pragma unroll
    for (int a = 0; a < 4; ++a)
#pragma unroll
        for (int c = 0; c < 4; ++c) acc[a][c] = 0ull;

    for (int ch = 0; ch < 8; ++ch) {
        int kbase = z * 512 + ch * 64;
#pragma unroll
        for (int u = 0; u < 4; ++u) {
            int f4 = u * 256 + tid;
            int row = f4 >> 4, c4 = f4 & 15;
            *(float4*)(Ti + row * GST + c4 * 4) =
                *(const float4*)(g_L + (size_t)(i0g + row) * DD + kbase + c4 * 4);
            *(float4*)(Tj + row * GST + c4 * 4) =
                *(const float4*)(g_L + (size_t)(j0g + row) * DD + kbase + c4 * 4);
        }
        __syncthreads();
#pragma unroll 4
        for (int kk = 0; kk < 64; kk += 4) {
            ulonglong2 a0 = *(const ulonglong2*)(Ti + (i0 + 0) * GST + kk);
            ulonglong2 a1 = *(const ulonglong2*)(Ti + (i0 + 1) * GST + kk);
            ulonglong2 a2 = *(const ulonglong2*)(Ti + (i0 + 2) * GST + kk);
            ulonglong2 a3 = *(const ulonglong2*)(Ti + (i0 + 3) * GST + kk);
            ulonglong2 b0 = *(const ulonglong2*)(Tj + (j0 + 0) * GST + kk);
            ulonglong2 b1 = *(const ulonglong2*)(Tj + (j0 + 1) * GST + kk);
            ulonglong2 b2 = *(const ulonglong2*)(Tj + (j0 + 2) * GST + kk);
            ulonglong2 b3 = *(const ulonglong2*)(Tj + (j0 + 3) * GST + kk);
            acc[0][0] = ffma2(a0.x, b0.x, acc[0][0]); acc[0][0] = ffma2(a0.y, b0.y, acc[0][0]);
            acc[0][1] = ffma2(a0.x, b1.x, acc[0][1]); acc[0][1] = ffma2(a0.y, b1.y, acc[0][1]);
            acc[0][2] = ffma2(a0.x, b2.x, acc[0][2]); acc[0][2] = ffma2(a0.y, b2.y, acc[0][2]);
            acc[0][3] = ffma2(a0.x, b3.x, acc[0][3]); acc[0][3] = ffma2(a0.y, b3.y, acc[0][3]);
            acc[1][0] = ffma2(a1.x, b0.x, acc[1][0]); acc[1][0] = ffma2(a1.y, b0.y, acc[1][0]);
            acc[1][1] = ffma2(a1.x, b1.x, acc[1][1]); acc[1][1] = ffma2(a1.y, b1.y, acc[1][1]);
            acc[1][2] = ffma2(a1.x, b2.x, acc[1][2]); acc[1][2] = ffma2(a1.y, b2.y, acc[1][2]);
            acc[1][3] = ffma2(a1.x, b3.x, acc[1][3]); acc[1][3] = ffma2(a1.y, b3.y, acc[1][3]);
            acc[2][0] = ffma2(a2.x, b0.x, acc[2][0]); acc[2][0] = ffma2(a2.y, b0.y, acc[2][0]);
            acc[2][1] = ffma2(a2.x, b1.x, acc[2][1]); acc[2][1] = ffma2(a2.y, b1.y, acc[2][1]);
            acc[2][2] = ffma2(a2.x, b2.x, acc[2][2]); acc[2][2] = ffma2(a2.y, b2.y, acc[2][2]);
            acc[2][3] = ffma2(a2.x, b3.x, acc[2][3]); acc[2][3] = ffma2(a2.y, b3.y, acc[2][3]);
            acc[3][0] = ffma2(a3.x, b0.x, acc[3][0]); acc[3][0] = ffma2(a3.y, b0.y, acc[3][0]);
            acc[3][1] = ffma2(a3.x, b1.x, acc[3][1]); acc[3][1] = ffma2(a3.y, b1.y, acc[3][1]);
            acc[3][2] = ffma2(a3.x, b2.x, acc[3][2]); acc[3][2] = ffma2(a3.y, b2.y, acc[3][2]);
            acc[3][3] = ffma2(a3.x, b3.x, acc[3][3]); acc[3][3] = ffma2(a3.y, b3.y, acc[3][3]);
        }
        __syncthreads();
    }
#pragma unroll
    for (int ii = 0; ii < 4; ++ii) {
        float4 o;
        float2 p0 = unpk(acc[ii][0]); o.x = p0.x + p0.y;
        float2 p1 = unpk(acc[ii][1]); o.y = p1.x + p1.y;
        float2 p2 = unpk(acc[ii][2]); o.z = p2.x + p2.y;
        float2 p3 = unpk(acc[ii][3]); o.w = p3.x + p3.y;
        *(float4*)(g_gramP + (size_t)z * 65536 +
                   (size_t)(i0g + i0 + ii) * NMAT + j0g + j0) = o;
    }
}

// ===== W from gram partials =====
__global__ __launch_bounds__(256) void W_kernel(const float* __restrict__ bwp) {
    int i = blockIdx.x, j = threadIdx.x;
    float g = 0.f;
#pragma unroll
    for (int z = 0; z < 8; ++z) g += g_gramP[(size_t)z * 65536 + (size_t)i * NMAT + j];
    float bw = *bwp;
    float coef = -0.5f / (bw * bw);
    const float eps = 1e-7f;
    float pds = g_sq[i] + g_sq[j] - 2.f * g + 2.f * eps * (g_s[j] - g_s[i]) + eps * eps * 4096.f;
    g_W[(size_t)i * NMAT + j] = expf(coef * pds);
}

// ===== row/col sums of W =====
__global__ __launch_bounds__(256) void sums_kernel() {
    __shared__ float r1[256], r2[256];
    int k = blockIdx.x, t = threadIdx.x;
    r1[t] = g_W[(size_t)k * NMAT + t];
    r2[t] = g_W[(size_t)t * NMAT + k];
    __syncthreads();
    for (int off = 128; off > 0; off >>= 1) {
        if (t < off) { r1[t] += r1[t + off]; r2[t] += r2[t + off]; }
        __syncthreads();
    }
    if (t == 0) { g_rs[k] = r1[0]; g_cs[k] = r2[0]; }
}

// ===== numK[k,c] = sum_j W[j,k]*L[j,c] =====
__global__ __launch_bounds__(256) void numK_kernel() {
    __shared__ float Ws[64 * 64], Ls[64 * 64];
    int tid = threadIdx.x;
    int c0 = blockIdx.x * 64, k0 = blockIdx.y * 64;
    int i0 = (tid >> 4) << 2, j0 = (tid & 15) << 2;
    unsigned long long acc[4][2];
#pragma unroll
    for (int c = 0; c < 4; ++c) { acc[c][0] = 0ull; acc[c][1] = 0ull; }

    for (int jc = 0; jc < 4; ++jc) {
#pragma unroll
        for (int u = 0; u < 4; ++u) {
            int f4 = tid * 4 + u;
            int jj = f4 >> 4, q4 = f4 & 15;
            *(float4*)(Ws + jj * 64 + q4 * 4) =
                *(const float4*)(g_W + (size_t)(jc * 64 + jj) * NMAT + k0 + q4 * 4);
            *(float4*)(Ls + jj * 64 + q4 * 4) =
                *(const float4*)(g_L + (size_t)(jc * 64 + jj) * DD + c0 + q4 * 4);
        }
        __syncthreads();
#pragma unroll 8
        for (int jj = 0; jj < 64; ++jj) {
            const ulonglong2 av = *(const ulonglong2*)(Ws + jj * 64 + i0);
            const float4 bv = *(const float4*)(Ls + jj * 64 + j0);
            unsigned long long b0 = bcast2(bv.x), b1 = bcast2(bv.y);
            unsigned long long b2 = bcast2(bv.z), b3 = bcast2(bv.w);
            acc[0][0] = ffma2(av.x, b0, acc[0][0]); acc[0][1] = ffma2(av.y, b0, acc[0][1]);
            acc[1][0] = ffma2(av.x, b1, acc[1][0]); acc[1][1] = ffma2(av.y, b1, acc[1][1]);
            acc[2][0] = ffma2(av.x, b2, acc[2][0]); acc[2][1] = ffma2(av.y, b2, acc[2][1]);
            acc[3][0] = ffma2(av.x, b3, acc[3][0]); acc[3][1] = ffma2(av.y, b3, acc[3][1]);
        }
        __syncthreads();
    }
#pragma unroll
    for (int c = 0; c < 4; ++c) {
#pragma unroll
        for (int r2 = 0; r2 < 2; ++r2) {
            float2 p = unpk(acc[c][r2]);
            int kk = k0 + i0 + 2 * r2;
            int cc = c0 + j0 + c;
            g_numK[(size_t)kk * DD + cc] = p.x;
            g_numK[(size_t)(kk + 1) * DD + cc] = p.y;
        }
    }
}

// ===== cheb_exp: Z in smem, Gershgorin bounds, Bessel coeffs, Clenshaw =====
__global__ __launch_bounds__(128) void cheb_exp_kernel(float* __restrict__ out) {
    extern __shared__ float sm[];
    float* Ys = sm;
    float* Bd0 = sm + 4096;
    float* Bd1 = sm + 12288;
    float* extra = sm + 20480;
    int b = blockIdx.x, tid = threadIdx.x;
    const float* Lb = g_L + (size_t)b * DD;
    const float* Nb = g_numK + (size_t)b * DD;
    float rs_ = g_rs[b], cs_ = g_cs[b];
    float fL = 1.f - cs_ / rs_;
    float fN = 1.f / rs_;

    int r = tid >> 1, q = tid & 1;
    float pa = 0.f, pd = 0.f;
#pragma unroll
    for (int u = 0; u < 8; ++u) {
        int cb = q * 32 + u * 4;
        int e = r * 64 + cb;
        float4 l = *(const float4*)(Lb + e);
        float4 n = *(const float4*)(Nb + e);
        float4 z;
        z.x = fmaf(fL, l.x, fN * n.x);
        z.y = fmaf(fL, l.y, fN * n.y);
        z.z = fmaf(fL, l.z, fN * n.z);
        z.w = fmaf(fL, l.w, fN * n.w);
        *(float4*)(Ys + e) = z;
        pa += fabsf(z.x) + fabsf(z.y) + fabsf(z.z) + fabsf(z.w);
        if (cb + 0 == r) pd = z.x;
        if (cb + 1 == r) pd = z.y;
        if (cb + 2 == r) pd = z.z;
        if (cb + 3 == r) pd = z.w;
    }
    Bd1[tid] = pa;
    Bd1[128 + tid] = pd;
    __syncthreads();
    if (tid < 64) {
        float ra = Bd1[2 * tid] + Bd1[2 * tid + 1];
        float dv = Bd1[128 + 2 * tid] + Bd1[128 + 2 * tid + 1];
        float off = ra - fabsf(dv);
        Bd1[256 + tid] = dv + off;
        Bd1[320 + tid] = dv - off;
    }
    __syncthreads();
    if (tid == 0) {
        float lo = Bd1[320], hi = Bd1[256];
        for (int i2 = 1; i2 < 64; ++i2) {
            lo = fminf(lo, Bd1[320 + i2]);
            hi = fmaxf(hi, Bd1[256 + i2]);
        }
        float m = 0.5f * (lo + hi);
        float h = 0.5f * (hi - lo) + 0.01f;
        if (h < 0.05f) h = 0.05f;
        extra[36] = m;
        extra[37] = h;
    }
    __syncthreads();
    if (tid <= K_EXP) {
        float m = extra[36], h2 = 0.5f * extra[37];
        int k = tid;
        float term = 1.f;
        for (int i2 = 1; i2 <= k; ++i2) term *= h2 / (float)i2;
        float ssum = term;
        for (int t = 1; t <= 48; ++t) {
            term *= (h2 * h2) / ((float)t * (float)(k + t));
            ssum += term;
            if (term < ssum * 1e-10f) break;
        }
        extra[k] = (k == 0 ? 1.f : 2.f) * expf(m) * ssum;
    }
    __syncthreads();

    const int i0 = (tid >> 4) << 3, j0 = (tid & 15) << 2;
    float tA[32], tB[32];
    scale_and_init(Ys, Bd0, tid, extra[36], 1.f / extra[37], extra[K_EXP], tA, tB, i0, j0);
    clenshaw_run<K_EXP>(Ys, Bd0, Bd1, extra, tA, tB, i0, j0);

    float* db = out + (size_t)b * DD;
#pragma unroll
    for (int rr = 0; rr < 8; ++rr)
        *(float4*)(db + (i0 + rr) * 64 + j0) =
            make_float4(tA[rr * 4], tA[rr * 4 + 1], tA[rr * 4 + 2], tA[rr * 4 + 3]);
}

// ================= launch =================
extern "C" void kernel_launch(void* const* d_in, const int* in_sizes, int n_in,
                              void* d_out, int out_size) {
    const float* X = (const float*)d_in[0];
    const float* bw = (const float*)d_in[1];
    float* out = (float*)d_out;
    (void)in_sizes; (void)n_in; (void)out_size;

    cudaFuncSetAttribute(cheb_log_kernel, cudaFuncAttributeMaxDynamicSharedMemorySize, SMEMX);
    cudaFuncSetAttribute(cheb_exp_kernel, cudaFuncAttributeMaxDynamicSharedMemorySize, SMEMX);

    cheb_log_kernel<<<NMAT, 128, SMEMX>>>(X);
    gram_kernel<<<dim3(4, 4, 8), 256>>>();
    W_kernel<<<NMAT, 256>>>(bw);
    sums_kernel<<<NMAT, 256>>>();
    numK_kernel<<<dim3(64, 4), 256>>>();
    cheb_exp_kernel<<<NMAT, 128, SMEMX>>>(out);
}

// round 11
// speedup vs baseline: 1.2847x; 1.2847x over previous
#include <cuda_runtime.h>
#include <math.h>

#define NMAT 256
#define DIM 64
#define DD 4096
#define K_LOG 13
#define K_EXP 11

// smem: Ys(4096 f) | B0(4096 f) | B1(4096 f) | extra(64 f)
#define SMEMX ((3 * 4096 + 64) * 4)

// ---------------- device scratch (no allocations allowed) ----------------
__device__ float g_L[NMAT * DD];
__device__ float g_numK[NMAT * DD];
__device__ float g_W[NMAT * NMAT];
__device__ float g_gramP[8 * NMAT * NMAT];
__device__ float g_sq[NMAT];
__device__ float g_s[NMAT];
__device__ float g_rs[NMAT];
__device__ float g_cs[NMAT];

// ---------------- packed f32x2 helpers ----------------
__device__ __forceinline__ unsigned long long ffma2(unsigned long long a,
                                                    unsigned long long b,
                                                    unsigned long long c) {
    unsigned long long d;
    asm("fma.rn.f32x2 %0, %1, %2, %3;" : "=l"(d) : "l"(a), "l"(b), "l"(c));
    return d;
}
__device__ __forceinline__ unsigned long long bcast2(float x) {
    unsigned long long d;
    unsigned int xi = __float_as_uint(x);
    asm("mov.b64 %0, {%1, %1};" : "=l"(d) : "r"(xi));
    return d;
}
__device__ __forceinline__ float2 unpk(unsigned long long v) {
    unsigned int a, b;
    asm("mov.b64 {%0, %1}, %2;" : "=r"(a), "=r"(b) : "l"(v));
    return make_float2(__uint_as_float(a), __uint_as_float(b));
}

// ============ one Clenshaw step: register-resident prev tile ============
// T (32 regs) holds b_{k+2} tile on entry, b_k tile on exit.
// BcR: compact b_{k+1} matrix (read via float4 + bcast2); BcW: store target.
template<bool STORE>
__device__ __forceinline__ void clen_step(const float* __restrict__ Ys,
                                          const float* __restrict__ BcR,
                                          float* __restrict__ BcW,
                                          float* T, int i0, int j0,
                                          float ck, float fac) {
    unsigned long long acc[4][4];
#pragma unroll
    for (int a = 0; a < 4; ++a)
#pragma unroll
        for (int c = 0; c < 4; ++c) acc[a][c] = 0ull;

#pragma unroll 8
    for (int k = 0; k < 64; ++k) {
        const ulonglong2 a01 = *(const ulonglong2*)(Ys + k * 64 + i0);
        const ulonglong2 a23 = *(const ulonglong2*)(Ys + k * 64 + i0 + 4);
        const float4 bv = *(const float4*)(BcR + k * 64 + j0);
        unsigned long long b0 = bcast2(bv.x), b1 = bcast2(bv.y);
        unsigned long long b2 = bcast2(bv.z), b3 = bcast2(bv.w);
        acc[0][0] = ffma2(a01.x, b0, acc[0][0]); acc[1][0] = ffma2(a01.y, b0, acc[1][0]);
        acc[2][0] = ffma2(a23.x, b0, acc[2][0]); acc[3][0] = ffma2(a23.y, b0, acc[3][0]);
        acc[0][1] = ffma2(a01.x, b1, acc[0][1]); acc[1][1] = ffma2(a01.y, b1, acc[1][1]);
        acc[2][1] = ffma2(a23.x, b1, acc[2][1]); acc[3][1] = ffma2(a23.y, b1, acc[3][1]);
        acc[0][2] = ffma2(a01.x, b2, acc[0][2]); acc[1][2] = ffma2(a01.y, b2, acc[1][2]);
        acc[2][2] = ffma2(a23.x, b2, acc[2][2]); acc[3][2] = ffma2(a23.y, b2, acc[3][2]);
        acc[0][3] = ffma2(a01.x, b3, acc[0][3]); acc[1][3] = ffma2(a01.y, b3, acc[1][3]);
        acc[2][3] = ffma2(a23.x, b3, acc[2][3]); acc[3][3] = ffma2(a23.y, b3, acc[3][3]);
    }

#pragma unroll
    for (int ip = 0; ip < 4; ++ip) {
        float2 p0 = unpk(acc[ip][0]), p1 = unpk(acc[ip][1]);
        float2 p2 = unpk(acc[ip][2]), p3 = unpk(acc[ip][3]);
        float vr[2][4] = {{p0.x, p1.x, p2.x, p3.x}, {p0.y, p1.y, p2.y, p3.y}};
#pragma unroll
        for (int t = 0; t < 2; ++t) {
            const int r = 2 * ip + t;
            const int gi = i0 + r;
            float4 nv;
            nv.x = fmaf(fac, vr[t][0], -T[r * 4 + 0]);
            nv.y = fmaf(fac, vr[t][1], -T[r * 4 + 1]);
            nv.z = fmaf(fac, vr[t][2], -T[r * 4 + 2]);
            nv.w = fmaf(fac, vr[t][3], -T[r * 4 + 3]);
            if (gi == j0 + 0) nv.x += ck;
            if (gi == j0 + 1) nv.y += ck;
            if (gi == j0 + 2) nv.z += ck;
            if (gi == j0 + 3) nv.w += ck;
            T[r * 4 + 0] = nv.x; T[r * 4 + 1] = nv.y;
            T[r * 4 + 2] = nv.z; T[r * 4 + 3] = nv.w;
            if (STORE)
                *(float4*)(BcW + gi * 64 + j0) = nv;
        }
    }
    if (STORE) __syncthreads();
}

// scale Ys in place, init B0 = cK*I (compact), tiles tA=0 / tB=cK-diag
__device__ __forceinline__ void scale_and_init(float* Ys, float* B0, int tid,
                                               float m, float invh, float cK,
                                               float* tA, float* tB, int i0, int j0) {
#pragma unroll
    for (int u = 0; u < 8; ++u) {
        int e = (u * 128 + tid) * 4;
        float4 x = *(const float4*)(Ys + e);
        int i = e >> 6, jb = e & 63;
        x.x = (x.x - ((jb + 0) == i ? m : 0.f)) * invh;
        x.y = (x.y - ((jb + 1) == i ? m : 0.f)) * invh;
        x.z = (x.z - ((jb + 2) == i ? m : 0.f)) * invh;
        x.w = (x.w - ((jb + 3) == i ? m : 0.f)) * invh;
        *(float4*)(Ys + e) = x;
        float4 bi;
        bi.x = ((jb + 0) == i) ? cK : 0.f;
        bi.y = ((jb + 1) == i) ? cK : 0.f;
        bi.z = ((jb + 2) == i) ? cK : 0.f;
        bi.w = ((jb + 3) == i) ? cK : 0.f;
        *(float4*)(B0 + e) = bi;
    }
#pragma unroll
    for (int r = 0; r < 8; ++r)
#pragma unroll
        for (int j = 0; j < 4; ++j) {
            tA[r * 4 + j] = 0.f;
            tB[r * 4 + j] = (i0 + r == j0 + j) ? cK : 0.f;
        }
    __syncthreads();
}

// steps k=K-1..1 (K-1 even -> K odd), then final k=0 -> result in tA
template<int K>
__device__ __forceinline__ void clenshaw_run(const float* Ys, float* B0, float* B1,
                                             const float* cc, float* tA, float* tB,
                                             int i0, int j0) {
    for (int s = 0; s < (K - 1) / 2; ++s) {
        float c1 = cc[K - 1 - 2 * s];
        float c2 = cc[K - 2 - 2 * s];
        clen_step<true>(Ys, B0, B1, tA, i0, j0, c1, 2.f);
        clen_step<true>(Ys, B1, B0, tB, i0, j0, c2, 2.f);
    }
    clen_step<false>(Ys, B0, nullptr, tA, i0, j0, cc[0], 1.f);
}

// ===== cheb_log: load, Gershgorin + power-iter bound, coeffs, Clenshaw, L + stats =====
__global__ __launch_bounds__(128) void cheb_log_kernel(const float* __restrict__ X) {
    extern __shared__ float sm[];
    float* Ys = sm;
    float* B0 = sm + 4096;
    float* B1 = sm + 8192;
    float* extra = sm + 12288;     // [0..K] coeffs, [36]=m, [37]=h
    int b = blockIdx.x, tid = threadIdx.x;
    const float* sb = X + (size_t)b * DD;

    int r = tid >> 1, q = tid & 1;
    float pa = 0.f;
#pragma unroll
    for (int u = 0; u < 8; ++u) {
        int cb = q * 32 + u * 4;
        float4 x = *(const float4*)(sb + r * 64 + cb);
        *(float4*)(Ys + r * 64 + cb) = x;
        pa += fabsf(x.x) + fabsf(x.y) + fabsf(x.z) + fabsf(x.w);
    }
    B1[tid] = pa;
    __syncthreads();
    if (tid < 64) B1[128 + tid] = B1[2 * tid] + B1[2 * tid + 1];

    // power iteration (19 matvecs), column-major reads
    float* v = B1 + 256;
    float* w = B1 + 320;
    if (tid < 64) v[tid] = 1.f + 0.0123f * (float)tid;
    __syncthreads();
    for (int it = 0; it < 19; ++it) {
        float p = 0.f;
#pragma unroll 8
        for (int c = 0; c < 32; ++c)
            p = fmaf(Ys[(q * 32 + c) * 64 + r], v[q * 32 + c], p);
        p += __shfl_xor_sync(0xffffffffu, p, 1);
        if (q == 0) w[r] = p;
        __syncthreads();
        if (it < 18) {
            if (tid < 64) v[tid] = w[tid] * 0.25f;
            __syncthreads();
        }
    }
    if (tid == 0) {
        float vw = 0.f, vv = 0.f;
        for (int t2 = 0; t2 < 64; ++t2) { vw += v[t2] * w[t2]; vv += v[t2] * v[t2]; }
        float rho = vw / vv;
        float gersh = 0.f;
        for (int t2 = 0; t2 < 64; ++t2) gersh = fmaxf(gersh, B1[128 + t2]);
        float bb = fminf(gersh + 1e-3f, fmaf(1.12f, rho, 0.45f));
        if (bb < 0.6f) bb = 0.6f;
        const float a = 0.49f;
        extra[36] = 0.5f * (a + bb);
        extra[37] = 0.5f * (bb - a);
    }
    __syncthreads();
    if (tid <= K_LOG) {
        float m = extra[36], h = extra[37];
        float beta = h / m;
        float s = sqrtf(fmaxf(1.f - beta * beta, 0.f));
        float qz = (1.f - s) / beta;
        if (tid == 0) extra[0] = logf(m) - logf(1.f + qz * qz);
        else {
            float qk = exp2f((float)tid * log2f(qz));
            extra[tid] = 2.f * ((tid & 1) ? 1.f : -1.f) * qk / (float)tid;
        }
    }
    __syncthreads();

    const int i0 = (tid >> 4) << 3, j0 = (tid & 15) << 2;
    float tA[32], tB[32];
    scale_and_init(Ys, B0, tid, extra[36], 1.f / extra[37], extra[K_LOG], tA, tB, i0, j0);
    clenshaw_run<K_LOG>(Ys, B0, B1, extra, tA, tB, i0, j0);

    float* db = g_L + (size_t)b * DD;
    float sqa = 0.f, ssum = 0.f;
#pragma unroll
    for (int rr = 0; rr < 8; ++rr) {
        float4 o = make_float4(tA[rr * 4], tA[rr * 4 + 1], tA[rr * 4 + 2], tA[rr * 4 + 3]);
        *(float4*)(db + (i0 + rr) * 64 + j0) = o;
        sqa = fmaf(o.x, o.x, fmaf(o.y, o.y, fmaf(o.z, o.z, fmaf(o.w, o.w, sqa))));
        ssum += o.x + o.y + o.z + o.w;
    }
    __syncthreads();
    B1[tid] = sqa;
    B1[128 + tid] = ssum;
    __syncthreads();
    for (int off = 64; off > 0; off >>= 1) {
        if (tid < off) { B1[tid] += B1[tid + off]; B1[128 + tid] += B1[128 + tid + off]; }
        __syncthreads();
    }
    if (tid == 0) { g_sq[b] = B1[0]; g_s[b] = B1[128]; }
}

// ===== gram: split-K GEMM, f32x2 packed along k =====
#define GST 68
__global__ __launch_bounds__(256) void gram_kernel() {
    __shared__ float Ti[64 * GST], Tj[64 * GST];
    int tid = threadIdx.x;
    int j0g = blockIdx.x * 64, i0g = blockIdx.y * 64, z = blockIdx.z;
    int ti = tid >> 4, tj = tid & 15;
    int i0 = ti * 4, j0 = tj * 4;

    unsigned long long acc[4][4];
#pragma unroll
    for (int a = 0; a < 4; ++a)
#pragma unroll
        for (int c = 0; c < 4; ++c) acc[a][c] = 0ull;

    for (int ch = 0; ch < 8; ++ch) {
        int kbase = z * 512 + ch * 64;
#pragma unroll
        for (int u = 0; u < 4; ++u) {
            int f4 = u * 256 + tid;
            int row = f4 >> 4, c4 = f4 & 15;
            *(float4*)(Ti + row * GST + c4 * 4) =
                *(const float4*)(g_L + (size_t)(i0g + row) * DD + kbase + c4 * 4);
            *(float4*)(Tj + row * GST + c4 * 4) =
                *(const float4*)(g_L + (size_t)(j0g + row) * DD + kbase + c4 * 4);
        }
        __syncthreads();
#pragma unroll 4
        for (int kk = 0; kk < 64; kk += 4) {
            ulonglong2 a0 = *(const ulonglong2*)(Ti + (i0 + 0) * GST + kk);
            ulonglong2 a1 = *(const ulonglong2*)(Ti + (i0 + 1) * GST + kk);
            ulonglong2 a2 = *(const ulonglong2*)(Ti + (i0 + 2) * GST + kk);
            ulonglong2 a3 = *(const ulonglong2*)(Ti + (i0 + 3) * GST + kk);
            ulonglong2 b0 = *(const ulonglong2*)(Tj + (j0 + 0) * GST + kk);
            ulonglong2 b1 = *(const ulonglong2*)(Tj + (j0 + 1) * GST + kk);
            ulonglong2 b2 = *(const ulonglong2*)(Tj + (j0 + 2) * GST + kk);
            ulonglong2 b3 = *(const ulonglong2*)(Tj + (j0 + 3) * GST + kk);
            acc[0][0] = ffma2(a0.x, b0.x, acc[0][0]); acc[0][0] = ffma2(a0.y, b0.y, acc[0][0]);
            acc[0][1] = ffma2(a0.x, b1.x, acc[0][1]); acc[0][1] = ffma2(a0.y, b1.y, acc[0][1]);
            acc[0][2] = ffma2(a0.x, b2.x, acc[0][2]); acc[0][2] = ffma2(a0.y, b2.y, acc[0][2]);
            acc[0][3] = ffma2(a0.x, b3.x, acc[0][3]); acc[0][3] = ffma2(a0.y, b3.y, acc[0][3]);
            acc[1][0] = ffma2(a1.x, b0.x, acc[1][0]); acc[1][0] = ffma2(a1.y, b0.y, acc[1][0]);
            acc[1][1] = ffma2(a1.x, b1.x, acc[1][1]); acc[1][1] = ffma2(a1.y, b1.y, acc[1][1]);
            acc[1][2] = ffma2(a1.x, b2.x, acc[1][2]); acc[1][2] = ffma2(a1.y, b2.y, acc[1][2]);
            acc[1][3] = ffma2(a1.x, b3.x, acc[1][3]); acc[1][3] = ffma2(a1.y, b3.y, acc[1][3]);
            acc[2][0] = ffma2(a2.x, b0.x, acc[2][0]); acc[2][0] = ffma2(a2.y, b0.y, acc[2][0]);
            acc[2][1] = ffma2(a2.x, b1.x, acc[2][1]); acc[2][1] = ffma2(a2.y, b1.y, acc[2][1]);
            acc[2][2] = ffma2(a2.x, b2.x, acc[2][2]); acc[2][2] = ffma2(a2.y, b2.y, acc[2][2]);
            acc[2][3] = ffma2(a2.x, b3.x, acc[2][3]); acc[2][3] = ffma2(a2.y, b3.y, acc[2][3]);
            acc[3][0] = ffma2(a3.x, b0.x, acc[3][0]); acc[3][0] = ffma2(a3.y, b0.y, acc[3][0]);
            acc[3][1] = ffma2(a3.x, b1.x, acc[3][1]); acc[3][1] = ffma2(a3.y, b1.y, acc[3][1]);
            acc[3][2] = ffma2(a3.x, b2.x, acc[3][2]); acc[3][2] = ffma2(a3.y, b2.y, acc[3][2]);
            acc[3][3] = ffma2(a3.x, b3.x, acc[3][3]); acc[3][3] = ffma2(a3.y, b3.y, acc[3][3]);
        }
        __syncthreads();
    }
#pragma unroll
    for (int ii = 0; ii < 4; ++ii) {
        float4 o;
        float2 p0 = unpk(acc[ii][0]); o.x = p0.x + p0.y;
        float2 p1 = unpk(acc[ii][1]); o.y = p1.x + p1.y;
        float2 p2 = unpk(acc[ii][2]); o.z = p2.x + p2.y;
        float2 p3 = unpk(acc[ii][3]); o.w = p3.x + p3.y;
        *(float4*)(g_gramP + (size_t)z * 65536 +
                   (size_t)(i0g + i0 + ii) * NMAT + j0g + j0) = o;
    }
}

// ===== W from gram partials =====
__global__ __launch_bounds__(256) void W_kernel(const float* __restrict__ bwp) {
    int i = blockIdx.x, j = threadIdx.x;
    float g = 0.f;
#pragma unroll
    for (int z = 0; z < 8; ++z) g += g_gramP[(size_t)z * 65536 + (size_t)i * NMAT + j];
    float bw = *bwp;
    float coef = -0.5f / (bw * bw);
    const float eps = 1e-7f;
    float pds = g_sq[i] + g_sq[j] - 2.f * g + 2.f * eps * (g_s[j] - g_s[i]) + eps * eps * 4096.f;
    g_W[(size_t)i * NMAT + j] = expf(coef * pds);
}

// ===== row/col sums of W =====
__global__ __launch_bounds__(256) void sums_kernel() {
    __shared__ float r1[256], r2[256];
    int k = blockIdx.x, t = threadIdx.x;
    r1[t] = g_W[(size_t)k * NMAT + t];
    r2[t] = g_W[(size_t)t * NMAT + k];
    __syncthreads();
    for (int off = 128; off > 0; off >>= 1) {
        if (t < off) { r1[t] += r1[t + off]; r2[t] += r2[t + off]; }
        __syncthreads();
    }
    if (t == 0) { g_rs[k] = r1[0]; g_cs[k] = r2[0]; }
}

// ===== numK[k,c] = sum_j W[j,k]*L[j,c] =====
__global__ __launch_bounds__(256) void numK_kernel() {
    __shared__ float Ws[64 * 64], Ls[64 * 64];
    int tid = threadIdx.x;
    int c0 = blockIdx.x * 64, k0 = blockIdx.y * 64;
    int i0 = (tid >> 4) << 2, j0 = (tid & 15) << 2;
    unsigned long long acc[4][2];
#pragma unroll
    for (int c = 0; c < 4; ++c) { acc[c][0] = 0ull; acc[c][1] = 0ull; }

    for (int jc = 0; jc < 4; ++jc) {
#pragma unroll
        for (int u = 0; u < 4; ++u) {
            int f4 = tid * 4 + u;
            int jj = f4 >> 4, q4 = f4 & 15;
            *(float4*)(Ws + jj * 64 + q4 * 4) =
                *(const float4*)(g_W + (size_t)(jc * 64 + jj) * NMAT + k0 + q4 * 4);
            *(float4*)(Ls + jj * 64 + q4 * 4) =
                *(const float4*)(g_L + (size_t)(jc * 64 + jj) * DD + c0 + q4 * 4);
        }
        __syncthreads();
#pragma unroll 8
        for (int jj = 0; jj < 64; ++jj) {
            const ulonglong2 av = *(const ulonglong2*)(Ws + jj * 64 + i0);
            const float4 bv = *(const float4*)(Ls + jj * 64 + j0);
            unsigned long long b0 = bcast2(bv.x), b1 = bcast2(bv.y);
            unsigned long long b2 = bcast2(bv.z), b3 = bcast2(bv.w);
            acc[0][0] = ffma2(av.x, b0, acc[0][0]); acc[0][1] = ffma2(av.y, b0, acc[0][1]);
            acc[1][0] = ffma2(av.x, b1, acc[1][0]); acc[1][1] = ffma2(av.y, b1, acc[1][1]);
            acc[2][0] = ffma2(av.x, b2, acc[2][0]); acc[2][1] = ffma2(av.y, b2, acc[2][1]);
            acc[3][0] = ffma2(av.x, b3, acc[3][0]); acc[3][1] = ffma2(av.y, b3, acc[3][1]);
        }
        __syncthreads();
    }
#pragma unroll
    for (int c = 0; c < 4; ++c) {
#pragma unroll
        for (int r2 = 0; r2 < 2; ++r2) {
            float2 p = unpk(acc[c][r2]);
            int kk = k0 + i0 + 2 * r2;
            int cc = c0 + j0 + c;
            g_numK[(size_t)kk * DD + cc] = p.x;
            g_numK[(size_t)(kk + 1) * DD + cc] = p.y;
        }
    }
}

// ===== cheb_exp: Z in smem, Gershgorin bounds, Bessel coeffs, Clenshaw =====
__global__ __launch_bounds__(128) void cheb_exp_kernel(float* __restrict__ out) {
    extern __shared__ float sm[];
    float* Ys = sm;
    float* B0 = sm + 4096;
    float* B1 = sm + 8192;
    float* extra = sm + 12288;
    int b = blockIdx.x, tid = threadIdx.x;
    const float* Lb = g_L + (size_t)b * DD;
    const float* Nb = g_numK + (size_t)b * DD;
    float rs_ = g_rs[b], cs_ = g_cs[b];
    float fL = 1.f - cs_ / rs_;
    float fN = 1.f / rs_;

    int r = tid >> 1, q = tid & 1;
    float pa = 0.f, pd = 0.f;
#pragma unroll
    for (int u = 0; u < 8; ++u) {
        int cb = q * 32 + u * 4;
        int e = r * 64 + cb;
        float4 l = *(const float4*)(Lb + e);
        float4 n = *(const float4*)(Nb + e);
        float4 z;
        z.x = fmaf(fL, l.x, fN * n.x);
        z.y = fmaf(fL, l.y, fN * n.y);
        z.z = fmaf(fL, l.z, fN * n.z);
        z.w = fmaf(fL, l.w, fN * n.w);
        *(float4*)(Ys + e) = z;
        pa += fabsf(z.x) + fabsf(z.y) + fabsf(z.z) + fabsf(z.w);
        if (cb + 0 == r) pd = z.x;
        if (cb + 1 == r) pd = z.y;
        if (cb + 2 == r) pd = z.z;
        if (cb + 3 == r) pd = z.w;
    }
    B1[tid] = pa;
    B1[128 + tid] = pd;
    __syncthreads();
    if (tid < 64) {
        float ra = B1[2 * tid] + B1[2 * tid + 1];
        float dv = B1[128 + 2 * tid] + B1[128 + 2 * tid + 1];
        float off = ra - fabsf(dv);
        B1[256 + tid] = dv + off;
        B1[320 + tid] = dv - off;
    }
    __syncthreads();
    if (tid == 0) {
        float lo = B1[320], hi = B1[256];
        for (int i2 = 1; i2 < 64; ++i2) {
            lo = fminf(lo, B1[320 + i2]);
            hi = fmaxf(hi, B1[256 + i2]);
        }
        float m = 0.5f * (lo + hi);
        float h = 0.5f * (hi - lo) + 0.01f;
        if (h < 0.05f) h = 0.05f;
        extra[36] = m;
        extra[37] = h;
    }
    __syncthreads();
    if (tid <= K_EXP) {
        float m = extra[36], h2 = 0.5f * extra[37];
        int k = tid;
        float term = 1.f;
        for (int i2 = 1; i2 <= k; ++i2) term *= h2 / (float)i2;
        float ssum = term;
        for (int t = 1; t <= 48; ++t) {
            term *= (h2 * h2) / ((float)t * (float)(k + t));
            ssum += term;
            if (term < ssum * 1e-10f) break;
        }
        extra[k] = (k == 0 ? 1.f : 2.f) * expf(m) * ssum;
    }
    __syncthreads();

    const int i0 = (tid >> 4) << 3, j0 = (tid & 15) << 2;
    float tA[32], tB[32];
    scale_and_init(Ys, B0, tid, extra[36], 1.f / extra[37], extra[K_EXP], tA, tB, i0, j0);
    clenshaw_run<K_EXP>(Ys, B0, B1, extra, tA, tB, i0, j0);

    float* db = out + (size_t)b * DD;
#pragma unroll
    for (int rr = 0; rr < 8; ++rr)
        *(float4*)(db + (i0 + rr) * 64 + j0) =
            make_float4(tA[rr * 4], tA[rr * 4 + 1], tA[rr * 4 + 2], tA[rr * 4 + 3]);
}

// ================= launch =================
extern "C" void kernel_launch(void* const* d_in, const int* in_sizes, int n_in,
                              void* d_out, int out_size) {
    const float* X = (const float*)d_in[0];
    const float* bw = (const float*)d_in[1];
    float* out = (float*)d_out;
    (void)in_sizes; (void)n_in; (void)out_size;

    cudaFuncSetAttribute(cheb_log_kernel, cudaFuncAttributeMaxDynamicSharedMemorySize, SMEMX);
    cudaFuncSetAttribute(cheb_exp_kernel, cudaFuncAttributeMaxDynamicSharedMemorySize, SMEMX);

    cheb_log_kernel<<<NMAT, 128, SMEMX>>>(X);
    gram_kernel<<<dim3(4, 4, 8), 256>>>();
    W_kernel<<<NMAT, 256>>>(bw);
    sums_kernel<<<NMAT, 256>>>();
    numK_kernel<<<dim3(64, 4), 256>>>();
    cheb_exp_kernel<<<NMAT, 128, SMEMX>>>(out);
}

// round 12
// speedup vs baseline: 1.3306x; 1.0357x over previous
#include <cuda_runtime.h>
#include <math.h>

#define NMAT 256
#define DIM 64
#define DD 4096
#define K_LOG 13
#define K_EXP 11

// dynamic smem: Ys | B1 | B2 | extra(64 floats: coeffs + m,h)
#define SMEMX (3 * DD * 4 + 64 * 4)

// ---------------- device scratch (no allocations allowed) ----------------
__device__ float g_L[NMAT * DD];
__device__ float g_numK[NMAT * DD];
__device__ float g_W[NMAT * NMAT];
__device__ float g_gramP[8 * NMAT * NMAT];
__device__ float g_sq[NMAT];
__device__ float g_s[NMAT];
__device__ float g_rs[NMAT];
__device__ float g_cs[NMAT];

// ---------------- packed f32x2 helpers ----------------
__device__ __forceinline__ unsigned long long ffma2(unsigned long long a,
                                                    unsigned long long b,
                                                    unsigned long long c) {
    unsigned long long d;
    asm("fma.rn.f32x2 %0, %1, %2, %3;" : "=l"(d) : "l"(a), "l"(b), "l"(c));
    return d;
}
__device__ __forceinline__ unsigned long long bcast2(float x) {
    unsigned long long d;
    unsigned int xi = __float_as_uint(x);
    asm("mov.b64 %0, {%1, %1};" : "=l"(d) : "r"(xi));
    return d;
}
__device__ __forceinline__ float2 unpk(unsigned long long v) {
    unsigned int a, b;
    asm("mov.b64 {%0, %1}, %2;" : "=r"(a), "=r"(b) : "l"(v));
    return make_float2(__uint_as_float(a), __uint_as_float(b));
}

// ============== Clenshaw step, 128 threads, 8x4 tile/thread ==============
// Bp_new = fac*Ys*Bc - Bp + ck*I.  Ys symmetric -> row-major reads for both.
__device__ __forceinline__ void chebstep(const float* __restrict__ Ys,
                                         const float* __restrict__ Bc,
                                         float* __restrict__ Bp,
                                         int i0, int j0, float ck, float fac) {
    unsigned long long acc[4][4];
#pragma unroll
    for (int a = 0; a < 4; ++a)
#pragma unroll
        for (int c = 0; c < 4; ++c) acc[a][c] = 0ull;

#pragma unroll 8
    for (int k = 0; k < DIM; ++k) {
        const ulonglong2 a01 = *reinterpret_cast<const ulonglong2*>(Ys + k * DIM + i0);
        const ulonglong2 a23 = *reinterpret_cast<const ulonglong2*>(Ys + k * DIM + i0 + 4);
        const float4 bv = *reinterpret_cast<const float4*>(Bc + k * DIM + j0);
        unsigned long long b0 = bcast2(bv.x), b1 = bcast2(bv.y);
        unsigned long long b2 = bcast2(bv.z), b3 = bcast2(bv.w);
        acc[0][0] = ffma2(a01.x, b0, acc[0][0]); acc[1][0] = ffma2(a01.y, b0, acc[1][0]);
        acc[2][0] = ffma2(a23.x, b0, acc[2][0]); acc[3][0] = ffma2(a23.y, b0, acc[3][0]);
        acc[0][1] = ffma2(a01.x, b1, acc[0][1]); acc[1][1] = ffma2(a01.y, b1, acc[1][1]);
        acc[2][1] = ffma2(a23.x, b1, acc[2][1]); acc[3][1] = ffma2(a23.y, b1, acc[3][1]);
        acc[0][2] = ffma2(a01.x, b2, acc[0][2]); acc[1][2] = ffma2(a01.y, b2, acc[1][2]);
        acc[2][2] = ffma2(a23.x, b2, acc[2][2]); acc[3][2] = ffma2(a23.y, b2, acc[3][2]);
        acc[0][3] = ffma2(a01.x, b3, acc[0][3]); acc[1][3] = ffma2(a01.y, b3, acc[1][3]);
        acc[2][3] = ffma2(a23.x, b3, acc[2][3]); acc[3][3] = ffma2(a23.y, b3, acc[3][3]);
    }

    float2 p[4][4];
#pragma unroll
    for (int a = 0; a < 4; ++a)
#pragma unroll
        for (int c = 0; c < 4; ++c) p[a][c] = unpk(acc[a][c]);

#pragma unroll
    for (int r = 0; r < 8; ++r) {
        const int ip = r >> 1;
        const int i = i0 + r;
        float4 old = *reinterpret_cast<const float4*>(Bp + i * DIM + j0);
        const float a0 = (r & 1) ? p[ip][0].y : p[ip][0].x;
        const float a1 = (r & 1) ? p[ip][1].y : p[ip][1].x;
        const float a2 = (r & 1) ? p[ip][2].y : p[ip][2].x;
        const float a3 = (r & 1) ? p[ip][3].y : p[ip][3].x;
        float4 nv;
        nv.x = fmaf(fac, a0, -old.x);
        nv.y = fmaf(fac, a1, -old.y);
        nv.z = fmaf(fac, a2, -old.z);
        nv.w = fmaf(fac, a3, -old.w);
        if (i == j0 + 0) nv.x += ck;
        if (i == j0 + 1) nv.y += ck;
        if (i == j0 + 2) nv.z += ck;
        if (i == j0 + 3) nv.w += ck;
        *reinterpret_cast<float4*>(Bp + i * DIM + j0) = nv;
    }
    __syncthreads();
}

// scale Ys in place: Ys = (Ysraw - m*I)/h ; init B1 = cK*I, B2 = 0   (128 threads)
__device__ __forceinline__ void scale_init(float* Ys, float* B1, float* B2,
                                           int tid, float m, float invh, float cK) {
#pragma unroll
    for (int u = 0; u < 8; ++u) {
        int e = (u * 128 + tid) * 4;
        float4 x = *reinterpret_cast<const float4*>(Ys + e);
        int i = e >> 6;
        int jb = e & 63;
        float4 y, bi;
        y.x = (x.x - ((jb + 0) == i ? m : 0.f)) * invh;
        y.y = (x.y - ((jb + 1) == i ? m : 0.f)) * invh;
        y.z = (x.z - ((jb + 2) == i ? m : 0.f)) * invh;
        y.w = (x.w - ((jb + 3) == i ? m : 0.f)) * invh;
        bi.x = ((jb + 0) == i) ? cK : 0.f;
        bi.y = ((jb + 1) == i) ? cK : 0.f;
        bi.z = ((jb + 2) == i) ? cK : 0.f;
        bi.w = ((jb + 3) == i) ? cK : 0.f;
        *reinterpret_cast<float4*>(Ys + e) = y;
        *reinterpret_cast<float4*>(B1 + e) = bi;
        *reinterpret_cast<float4*>(B2 + e) = make_float4(0.f, 0.f, 0.f, 0.f);
    }
    __syncthreads();
}

// ===== cheb_log: load X, Gershgorin + power-iter bound, coeffs, Clenshaw, L + stats =====
__global__ __launch_bounds__(128) void cheb_log_kernel(const float* __restrict__ X) {
    extern __shared__ float sm[];
    float* Ys = sm;
    float* B1 = sm + DD;
    float* B2 = sm + 2 * DD;
    float* extra = sm + 3 * DD;       // [0..K] coeffs, [36]=m, [37]=h
    int b = blockIdx.x, tid = threadIdx.x;
    const float* sb = X + (size_t)b * DD;

    // load raw X into Ys + per-thread abs half-row sum
    int r = tid >> 1, q = tid & 1;
    float pa = 0.f;
#pragma unroll
    for (int u = 0; u < 8; ++u) {
        int cb = q * 32 + u * 4;
        float4 x = *reinterpret_cast<const float4*>(sb + r * 64 + cb);
        *reinterpret_cast<float4*>(Ys + r * 64 + cb) = x;
        pa += fabsf(x.x) + fabsf(x.y) + fabsf(x.z) + fabsf(x.w);
    }
    B1[tid] = pa;
    __syncthreads();
    if (tid < 64) B1[128 + tid] = B1[2 * tid] + B1[2 * tid + 1];

    // power iteration (19 matvecs) for a tight lambda_max estimate
    float* v = B1 + 256;
    float* w = B1 + 320;
    if (tid < 64) v[tid] = 1.f + 0.0123f * (float)tid;
    __syncthreads();
    for (int it = 0; it < 19; ++it) {
        float p = 0.f;
#pragma unroll 8
        for (int c = 0; c < 32; ++c)
            p = fmaf(Ys[(q * 32 + c) * 64 + r], v[q * 32 + c], p);
        p += __shfl_xor_sync(0xffffffffu, p, 1);
        if (q == 0) w[r] = p;
        __syncthreads();
        if (it < 18) {
            if (tid < 64) v[tid] = w[tid] * 0.25f;   // rescale vs overflow
            __syncthreads();
        }
    }
    if (tid == 0) {
        float vw = 0.f, vv = 0.f;
        for (int t2 = 0; t2 < 64; ++t2) { vw += v[t2] * w[t2]; vv += v[t2] * v[t2]; }
        float rho = vw / vv;
        float gersh = 0.f;
        for (int t2 = 0; t2 < 64; ++t2) gersh = fmaxf(gersh, B1[128 + t2]);
        float bb = fminf(gersh + 1e-3f, fmaf(1.12f, rho, 0.45f));
        if (bb < 0.6f) bb = 0.6f;
        const float a = 0.49f;
        extra[36] = 0.5f * (a + bb);
        extra[37] = 0.5f * (bb - a);
    }
    __syncthreads();
    if (tid <= K_LOG) {
        float m = extra[36], h = extra[37];
        float beta = h / m;
        float s = sqrtf(fmaxf(1.f - beta * beta, 0.f));
        float qz = (1.f - s) / beta;
        if (tid == 0) extra[0] = logf(m) - logf(1.f + qz * qz);
        else {
            float qk = exp2f((float)tid * log2f(qz));
            extra[tid] = 2.f * ((tid & 1) ? 1.f : -1.f) * qk / (float)tid;
        }
    }
    __syncthreads();

    const float m = extra[36], invh = 1.f / extra[37];
    scale_init(Ys, B1, B2, tid, m, invh, extra[K_LOG]);

    const int i0 = (tid >> 4) << 3, j0 = (tid & 15) << 2;
    float* Bc = B1;
    float* Bp = B2;
    for (int k = K_LOG - 1; k >= 1; --k) {
        chebstep(Ys, Bc, Bp, i0, j0, extra[k], 2.f);
        float* tp = Bc; Bc = Bp; Bp = tp;
    }
    chebstep(Ys, Bc, Bp, i0, j0, extra[0], 1.f);

    // store L + fused stats (sq, s)
    float* db = g_L + (size_t)b * DD;
    float sqa = 0.f, ssum = 0.f;
#pragma unroll
    for (int u = 0; u < 8; ++u) {
        int e = (u * 128 + tid) * 4;
        float4 vv4 = *reinterpret_cast<const float4*>(Bp + e);
        *reinterpret_cast<float4*>(db + e) = vv4;
        sqa = fmaf(vv4.x, vv4.x, fmaf(vv4.y, vv4.y, fmaf(vv4.z, vv4.z, fmaf(vv4.w, vv4.w, sqa))));
        ssum += vv4.x + vv4.y + vv4.z + vv4.w;
    }
    __syncthreads();            // Ys no longer needed -> reuse for reduce
    Ys[tid] = sqa;
    Ys[128 + tid] = ssum;
    __syncthreads();
    for (int off = 64; off > 0; off >>= 1) {
        if (tid < off) { Ys[tid] += Ys[tid + off]; Ys[128 + tid] += Ys[128 + tid + off]; }
        __syncthreads();
    }
    if (tid == 0) { g_sq[b] = Ys[0]; g_s[b] = Ys[128]; }
}

// ===== gram: split-K GEMM, f32x2 packed along k =====
#define GST 68
__global__ __launch_bounds__(256) void gram_kernel() {
    __shared__ float Ti[64 * GST], Tj[64 * GST];
    int tid = threadIdx.x;
    int j0g = blockIdx.x * 64, i0g = blockIdx.y * 64, z = blockIdx.z;
    int ti = tid >> 4, tj = tid & 15;
    int i0 = ti * 4, j0 = tj * 4;

    unsigned long long acc[4][4];
#pragma unroll
    for (int a = 0; a < 4; ++a)
#pragma unroll
        for (int c = 0; c < 4; ++c) acc[a][c] = 0ull;

    for (int ch = 0; ch < 8; ++ch) {
        int kbase = z * 512 + ch * 64;
#pragma unroll
        for (int u = 0; u < 4; ++u) {
            int f4 = u * 256 + tid;
            int row = f4 >> 4, c4 = f4 & 15;
            *reinterpret_cast<float4*>(Ti + row * GST + c4 * 4) =
                *reinterpret_cast<const float4*>(g_L + (size_t)(i0g + row) * DD + kbase + c4 * 4);
            *reinterpret_cast<float4*>(Tj + row * GST + c4 * 4) =
                *reinterpret_cast<const float4*>(g_L + (size_t)(j0g + row) * DD + kbase + c4 * 4);
        }
        __syncthreads();
#pragma unroll 4
        for (int kk = 0; kk < 64; kk += 4) {
            ulonglong2 a0 = *reinterpret_cast<const ulonglong2*>(Ti + (i0 + 0) * GST + kk);
            ulonglong2 a1 = *reinterpret_cast<const ulonglong2*>(Ti + (i0 + 1) * GST + kk);
            ulonglong2 a2 = *reinterpret_cast<const ulonglong2*>(Ti + (i0 + 2) * GST + kk);
            ulonglong2 a3 = *reinterpret_cast<const ulonglong2*>(Ti + (i0 + 3) * GST + kk);
            ulonglong2 b0 = *reinterpret_cast<const ulonglong2*>(Tj + (j0 + 0) * GST + kk);
            ulonglong2 b1 = *reinterpret_cast<const ulonglong2*>(Tj + (j0 + 1) * GST + kk);
            ulonglong2 b2 = *reinterpret_cast<const ulonglong2*>(Tj + (j0 + 2) * GST + kk);
            ulonglong2 b3 = *reinterpret_cast<const ulonglong2*>(Tj + (j0 + 3) * GST + kk);
            acc[0][0] = ffma2(a0.x, b0.x, acc[0][0]); acc[0][0] = ffma2(a0.y, b0.y, acc[0][0]);
            acc[0][1] = ffma2(a0.x, b1.x, acc[0][1]); acc[0][1] = ffma2(a0.y, b1.y, acc[0][1]);
            acc[0][2] = ffma2(a0.x, b2.x, acc[0][2]); acc[0][2] = ffma2(a0.y, b2.y, acc[0][2]);
            acc[0][3] = ffma2(a0.x, b3.x, acc[0][3]); acc[0][3] = ffma2(a0.y, b3.y, acc[0][3]);
            acc[1][0] = ffma2(a1.x, b0.x, acc[1][0]); acc[1][0] = ffma2(a1.y, b0.y, acc[1][0]);
            acc[1][1] = ffma2(a1.x, b1.x, acc[1][1]); acc[1][1] = ffma2(a1.y, b1.y, acc[1][1]);
            acc[1][2] = ffma2(a1.x, b2.x, acc[1][2]); acc[1][2] = ffma2(a1.y, b2.y, acc[1][2]);
            acc[1][3] = ffma2(a1.x, b3.x, acc[1][3]); acc[1][3] = ffma2(a1.y, b3.y, acc[1][3]);
            acc[2][0] = ffma2(a2.x, b0.x, acc[2][0]); acc[2][0] = ffma2(a2.y, b0.y, acc[2][0]);
            acc[2][1] = ffma2(a2.x, b1.x, acc[2][1]); acc[2][1] = ffma2(a2.y, b1.y, acc[2][1]);
            acc[2][2] = ffma2(a2.x, b2.x, acc[2][2]); acc[2][2] = ffma2(a2.y, b2.y, acc[2][2]);
            acc[2][3] = ffma2(a2.x, b3.x, acc[2][3]); acc[2][3] = ffma2(a2.y, b3.y, acc[2][3]);
            acc[3][0] = ffma2(a3.x, b0.x, acc[3][0]); acc[3][0] = ffma2(a3.y, b0.y, acc[3][0]);
            acc[3][1] = ffma2(a3.x, b1.x, acc[3][1]); acc[3][1] = ffma2(a3.y, b1.y, acc[3][1]);
            acc[3][2] = ffma2(a3.x, b2.x, acc[3][2]); acc[3][2] = ffma2(a3.y, b2.y, acc[3][2]);
            acc[3][3] = ffma2(a3.x, b3.x, acc[3][3]); acc[3][3] = ffma2(a3.y, b3.y, acc[3][3]);
        }
        __syncthreads();
    }
#pragma unroll
    for (int ii = 0; ii < 4; ++ii) {
        float4 o;
        float2 p0 = unpk(acc[ii][0]); o.x = p0.x + p0.y;
        float2 p1 = unpk(acc[ii][1]); o.y = p1.x + p1.y;
        float2 p2 = unpk(acc[ii][2]); o.z = p2.x + p2.y;
        float2 p3 = unpk(acc[ii][3]); o.w = p3.x + p3.y;
        *reinterpret_cast<float4*>(g_gramP + (size_t)z * 65536 +
                                   (size_t)(i0g + i0 + ii) * NMAT + j0g + j0) = o;
    }
}

// ===== W from gram partials =====
__global__ __launch_bounds__(256) void W_kernel(const float* __restrict__ bwp) {
    int i = blockIdx.x, j = threadIdx.x;
    float g = 0.f;
#pragma unroll
    for (int z = 0; z < 8; ++z) g += g_gramP[(size_t)z * 65536 + (size_t)i * NMAT + j];
    float bw = *bwp;
    float coef = -0.5f / (bw * bw);
    const float eps = 1e-7f;
    float pds = g_sq[i] + g_sq[j] - 2.f * g + 2.f * eps * (g_s[j] - g_s[i]) + eps * eps * 4096.f;
    g_W[(size_t)i * NMAT + j] = expf(coef * pds);
}

// ===== row/col sums of W =====
__global__ __launch_bounds__(256) void sums_kernel() {
    __shared__ float r1[256], r2[256];
    int k = blockIdx.x, t = threadIdx.x;
    r1[t] = g_W[(size_t)k * NMAT + t];
    r2[t] = g_W[(size_t)t * NMAT + k];
    __syncthreads();
    for (int off = 128; off > 0; off >>= 1) {
        if (t < off) { r1[t] += r1[t + off]; r2[t] += r2[t + off]; }
        __syncthreads();
    }
    if (t == 0) { g_rs[k] = r1[0]; g_cs[k] = r2[0]; }
}

// ===== numK[k,c] = sum_j W[j,k]*L[j,c] =====
__global__ __launch_bounds__(256) void numK_kernel() {
    __shared__ float Ws[64 * 64], Ls[64 * 64];
    int tid = threadIdx.x;
    int c0 = blockIdx.x * 64, k0 = blockIdx.y * 64;
    int i0 = (tid >> 4) << 2, j0 = (tid & 15) << 2;
    unsigned long long acc[4][2];
#pragma unroll
    for (int c = 0; c < 4; ++c) { acc[c][0] = 0ull; acc[c][1] = 0ull; }

    for (int jc = 0; jc < 4; ++jc) {
#pragma unroll
        for (int u = 0; u < 4; ++u) {
            int f4 = tid * 4 + u;
            int jj = f4 >> 4, q4 = f4 & 15;
            *reinterpret_cast<float4*>(Ws + jj * 64 + q4 * 4) =
                *reinterpret_cast<const float4*>(g_W + (size_t)(jc * 64 + jj) * NMAT + k0 + q4 * 4);
            *reinterpret_cast<float4*>(Ls + jj * 64 + q4 * 4) =
                *reinterpret_cast<const float4*>(g_L + (size_t)(jc * 64 + jj) * DD + c0 + q4 * 4);
        }
        __syncthreads();
#pragma unroll 8
        for (int jj = 0; jj < 64; ++jj) {
            const ulonglong2 av = *reinterpret_cast<const ulonglong2*>(Ws + jj * 64 + i0);
            const float4 bv = *reinterpret_cast<const float4*>(Ls + jj * 64 + j0);
            unsigned long long b0 = bcast2(bv.x), b1 = bcast2(bv.y);
            unsigned long long b2 = bcast2(bv.z), b3 = bcast2(bv.w);
            acc[0][0] = ffma2(av.x, b0, acc[0][0]); acc[0][1] = ffma2(av.y, b0, acc[0][1]);
            acc[1][0] = ffma2(av.x, b1, acc[1][0]); acc[1][1] = ffma2(av.y, b1, acc[1][1]);
            acc[2][0] = ffma2(av.x, b2, acc[2][0]); acc[2][1] = ffma2(av.y, b2, acc[2][1]);
            acc[3][0] = ffma2(av.x, b3, acc[3][0]); acc[3][1] = ffma2(av.y, b3, acc[3][1]);
        }
        __syncthreads();
    }
#pragma unroll
    for (int c = 0; c < 4; ++c) {
#pragma unroll
        for (int r2 = 0; r2 < 2; ++r2) {
            float2 p = unpk(acc[c][r2]);
            int kk = k0 + i0 + 2 * r2;
            int cc = c0 + j0 + c;
            g_numK[(size_t)kk * DD + cc] = p.x;
            g_numK[(size_t)(kk + 1) * DD + cc] = p.y;
        }
    }
}

// ===== cheb_exp: build Z in smem, bounds, Bessel coeffs, Clenshaw =====
__global__ __launch_bounds__(128) void cheb_exp_kernel(float* __restrict__ out) {
    extern __shared__ float sm[];
    float* Ys = sm;
    float* B1 = sm + DD;
    float* B2 = sm + 2 * DD;
    float* extra = sm + 3 * DD;
    int b = blockIdx.x, tid = threadIdx.x;
    const float* Lb = g_L + (size_t)b * DD;
    const float* Nb = g_numK + (size_t)b * DD;
    float rs_ = g_rs[b], cs_ = g_cs[b];
    float fL = 1.f - cs_ / rs_;
    float fN = 1.f / rs_;

    // Z into Ys + Gershgorin pieces (half-row per thread)
    int r = tid >> 1, q = tid & 1;
    float pa = 0.f, pd = 0.f;
#pragma unroll
    for (int u = 0; u < 8; ++u) {
        int cb = q * 32 + u * 4;
        int e = r * 64 + cb;
        float4 l = *reinterpret_cast<const float4*>(Lb + e);
        float4 n = *reinterpret_cast<const float4*>(Nb + e);
        float4 z;
        z.x = fmaf(fL, l.x, fN * n.x);
        z.y = fmaf(fL, l.y, fN * n.y);
        z.z = fmaf(fL, l.z, fN * n.z);
        z.w = fmaf(fL, l.w, fN * n.w);
        *reinterpret_cast<float4*>(Ys + e) = z;
        pa += fabsf(z.x) + fabsf(z.y) + fabsf(z.z) + fabsf(z.w);
        if (cb + 0 == r) pd = z.x;
        if (cb + 1 == r) pd = z.y;
        if (cb + 2 == r) pd = z.z;
        if (cb + 3 == r) pd = z.w;
    }
    B1[tid] = pa;
    B1[128 + tid] = pd;
    __syncthreads();
    if (tid < 64) {
        float ra = B1[2 * tid] + B1[2 * tid + 1];
        float dv = B1[128 + 2 * tid] + B1[128 + 2 * tid + 1];
        float off = ra - fabsf(dv);
        B1[256 + tid] = dv + off;   // hi
        B1[320 + tid] = dv - off;   // lo
    }
    __syncthreads();
    if (tid == 0) {
        float lo = B1[320], hi = B1[256];
        for (int i2 = 1; i2 < 64; ++i2) { lo = fminf(lo, B1[320 + i2]); hi = fmaxf(hi, B1[256 + i2]); }
        float m = 0.5f * (lo + hi);
        float h = 0.5f * (hi - lo) + 0.01f;
        if (h < 0.05f) h = 0.05f;
        extra[36] = m;
        extra[37] = h;
    }
    __syncthreads();
    if (tid <= K_EXP) {
        float m = extra[36], h2 = 0.5f * extra[37];
        int k = tid;
        float term = 1.f;
        for (int i2 = 1; i2 <= k; ++i2) term *= h2 / (float)i2;
        float ssum = term;
        for (int t = 1; t <= 48; ++t) {
            term *= (h2 * h2) / ((float)t * (float)(k + t));
            ssum += term;
            if (term < ssum * 1e-10f) break;
        }
        extra[k] = (k == 0 ? 1.f : 2.f) * expf(m) * ssum;
    }
    __syncthreads();

    const float m = extra[36], invh = 1.f / extra[37];
    scale_init(Ys, B1, B2, tid, m, invh, extra[K_EXP]);

    const int i0 = (tid >> 4) << 3, j0 = (tid & 15) << 2;
    float* Bc = B1;
    float* Bp = B2;
    for (int k = K_EXP - 1; k >= 1; --k) {
        chebstep(Ys, Bc, Bp, i0, j0, extra[k], 2.f);
        float* tp = Bc; Bc = Bp; Bp = tp;
    }
    chebstep(Ys, Bc, Bp, i0, j0, extra[0], 1.f);

    float* db = out + (size_t)b * DD;
#pragma unroll
    for (int u = 0; u < 8; ++u) {
        int e = (u * 128 + tid) * 4;
        *reinterpret_cast<float4*>(db + e) = *reinterpret_cast<const float4*>(Bp + e);
    }
}

// ================= launch =================
extern "C" void kernel_launch(void* const* d_in, const int* in_sizes, int n_in,
                              void* d_out, int out_size) {
    const float* X = (const float*)d_in[0];
    const float* bw = (const float*)d_in[1];
    float* out = (float*)d_out;
    (void)in_sizes; (void)n_in; (void)out_size;

    cudaFuncSetAttribute(cheb_log_kernel, cudaFuncAttributeMaxDynamicSharedMemorySize, SMEMX);
    cudaFuncSetAttribute(cheb_exp_kernel, cudaFuncAttributeMaxDynamicSharedMemorySize, SMEMX);

    cheb_log_kernel<<<NMAT, 128, SMEMX>>>(X);
    gram_kernel<<<dim3(4, 4, 8), 256>>>();
    W_kernel<<<NMAT, 256>>>(bw);
    sums_kernel<<<NMAT, 256>>>();
    numK_kernel<<<dim3(64, 4), 256>>>();
    cheb_exp_kernel<<<NMAT, 128, SMEMX>>>(out);
}